// round 1
// baseline (speedup 1.0000x reference)
#include <cuda_runtime.h>
#include <cstdint>
#include <cstdio>

// SeparableAttention fused kernel (exact fp32, packed f32x2 FMA path).
//
// Math (per (b,h) tile, X = x[b,:,h,:] of shape [256 c][64 w]):
//   q[w]  = Wq.X[:,w] + bq         (Wq = Wqkv row 0)
//   s     = softmax(q)             (over w, sums to 1)
//   xs[c] = sum_w X[c,w] s[w]
//   cv[c] = Wk[c,:].xs + bk[c]     (K-GEMM eliminated since sum(s)=1)
//   v     = Wv.X + bv ; g = relu(v) * cv[c]
//   out   = Wout.g + bout
//
// Grid: 2048 blocks = (b,h); Block: 256 threads; each thread owns an
// 8c x 8w register tile (32 packed f32x2 accumulators).

#define XS_STRIDE 68    // 64 + 4 pad: float4-aligned rows
#define WC_STRIDE 265   // 256 + 9 pad: conflict-free chunk store & read

#define SMEM_FLOATS (256 * XS_STRIDE + 32 * WC_STRIDE + 256 + 64 + 64 + 256 + 256 + 4)

__device__ __forceinline__ unsigned long long bcast2(float w) {
    unsigned long long r;
    asm("mov.b64 %0, {%1, %1};" : "=l"(r) : "f"(w));
    return r;
}
__device__ __forceinline__ void ffma2(unsigned long long& d, unsigned long long a,
                                      unsigned long long b) {
    asm("fma.rn.f32x2 %0, %1, %2, %0;" : "+l"(d) : "l"(a), "l"(b));
}
__device__ __forceinline__ void unpack2(unsigned long long v, float& lo, float& hi) {
    asm("mov.b64 {%0, %1}, %2;" : "=f"(lo), "=f"(hi) : "l"(v));
}
__device__ __forceinline__ unsigned long long pack2(float lo, float hi) {
    unsigned long long r;
    asm("mov.b64 %0, {%1, %2};" : "=l"(r) : "f"(lo), "f"(hi));
    return r;
}

// One chunked 256x64x256 GEMM: acc[j][p] (+)= W[c0+j, e] * X[e, w0 + 2p..2p+1]
// Wg4: global weight base, element (r, e) at float index r*256 + e.
__device__ __forceinline__ void gemm_chunked(const float4* __restrict__ Wg4,
                                             const float* Xs, float* Wc,
                                             unsigned long long acc[8][4],
                                             int tid, int c0, int w0)
{
    for (int kc = 0; kc < 8; kc++) {
        __syncthreads();  // previous chunk consumed (or Xs/g writes visible)
        #pragma unroll
        for (int k = 0; k < 8; k++) {
            int idx = tid + k * 256;
            int e4 = idx & 7;         // which float4 within the 32-wide chunk
            int r  = idx >> 3;        // weight row (output channel)
            float4 v = __ldg(&Wg4[r * 64 + kc * 8 + e4]);
            int el = 4 * e4;
            Wc[(el + 0) * WC_STRIDE + r] = v.x;
            Wc[(el + 1) * WC_STRIDE + r] = v.y;
            Wc[(el + 2) * WC_STRIDE + r] = v.z;
            Wc[(el + 3) * WC_STRIDE + r] = v.w;
        }
        __syncthreads();
        #pragma unroll 8
        for (int el = 0; el < 32; el++) {
            int e = kc * 32 + el;
            const unsigned long long* xr =
                (const unsigned long long*)&Xs[e * XS_STRIDE + w0];
            unsigned long long xp0 = xr[0], xp1 = xr[1], xp2 = xr[2], xp3 = xr[3];
            const float* wrow = &Wc[el * WC_STRIDE + c0];
            #pragma unroll
            for (int j = 0; j < 8; j++) {
                unsigned long long wp = bcast2(wrow[j]);
                ffma2(acc[j][0], wp, xp0);
                ffma2(acc[j][1], wp, xp1);
                ffma2(acc[j][2], wp, xp2);
                ffma2(acc[j][3], wp, xp3);
            }
        }
    }
}

__global__ __launch_bounds__(256, 2)
void sepattn_kernel(const float* __restrict__ x,
                    const float* __restrict__ Wqkv,
                    const float* __restrict__ bqkv,
                    const float* __restrict__ Wout,
                    const float* __restrict__ bout,
                    float* __restrict__ out)
{
    extern __shared__ float smem[];
    float* Xs   = smem;                        // 256*68  (X tile, later g tile)
    float* Wc   = Xs   + 256 * XS_STRIDE;      // 32*265  (weight K-chunk, [el][r])
    float* Wq_s = Wc   + 32 * WC_STRIDE;       // 256
    float* q_s  = Wq_s + 256;                  // 64
    float* s_s  = q_s  + 64;                   // 64
    float* xs_s = s_s  + 64;                   // 256
    float* cv_s = xs_s + 256;                  // 256
    float* red  = cv_s + 256;                  // 2

    const int tid = threadIdx.x;
    const int b = blockIdx.x >> 6;
    const int h = blockIdx.x & 63;

    // ---- load X tile (256 c x 64 w) into smem ----
    const float4* x4 = (const float4*)(x + (size_t)b * 256 * 4096 + (size_t)h * 64);
    #pragma unroll
    for (int k = 0; k < 16; k++) {
        int idx = tid + k * 256;
        int w4 = idx & 15, c = idx >> 4;
        float4 v = __ldg(&x4[c * 1024 + w4]);
        *(float4*)&Xs[c * XS_STRIDE + 4 * w4] = v;
    }
    if (tid < 64) {  // stage Wq (row 0 of Wqkv)
        float4 v = __ldg(&((const float4*)Wqkv)[tid]);
        *(float4*)&Wq_s[4 * tid] = v;
    }
    __syncthreads();

    // ---- q[w] = Wq . X[:,w] + bq ----
    if (tid < 64) {
        float acc = __ldg(&bqkv[0]);
        #pragma unroll 8
        for (int c = 0; c < 256; c++)
            acc = fmaf(Wq_s[c], Xs[c * XS_STRIDE + tid], acc);
        q_s[tid] = acc;
    }
    __syncthreads();
    // ---- softmax over 64 ----
    if (tid < 32) {
        float m = fmaxf(q_s[tid], q_s[tid + 32]);
        #pragma unroll
        for (int o = 16; o > 0; o >>= 1) m = fmaxf(m, __shfl_xor_sync(0xffffffffu, m, o));
        if (tid == 0) red[0] = m;
    }
    __syncthreads();
    if (tid < 64) q_s[tid] = __expf(q_s[tid] - red[0]);
    __syncthreads();
    if (tid < 32) {
        float s = q_s[tid] + q_s[tid + 32];
        #pragma unroll
        for (int o = 16; o > 0; o >>= 1) s += __shfl_xor_sync(0xffffffffu, s, o);
        if (tid == 0) red[1] = 1.0f / s;
    }
    __syncthreads();
    if (tid < 64) s_s[tid] = q_s[tid] * red[1];
    __syncthreads();

    // ---- xs[c] = sum_w X[c,w] * s[w] ----
    {
        float acc = 0.f;
        #pragma unroll 8
        for (int w = 0; w < 64; w++)
            acc = fmaf(Xs[tid * XS_STRIDE + w], s_s[w], acc);
        xs_s[tid] = acc;
    }
    __syncthreads();
    // ---- cv[c] = Wk[c,:] . xs + bk[c]   (Wk = Wqkv rows 1..256) ----
    {
        const float4* wk4 = (const float4*)(Wqkv + (size_t)(1 + tid) * 256);
        const float4* xs4 = (const float4*)xs_s;
        float acc = __ldg(&bqkv[1 + tid]);
        #pragma unroll 8
        for (int j = 0; j < 64; j++) {
            float4 wv = __ldg(&wk4[j]);
            float4 xv = xs4[j];
            acc += wv.x * xv.x + wv.y * xv.y + wv.z * xv.z + wv.w * xv.w;
        }
        cv_s[tid] = acc;
    }
    // (gemm_chunked begins with __syncthreads — covers cv_s visibility)

    const int c0 = (tid >> 3) * 8;
    const int w0 = (tid & 7) * 8;
    unsigned long long acc[8][4];

    // ================= V GEMM: v = Wv.X (+bv) =================
    #pragma unroll
    for (int j = 0; j < 8; j++)
        #pragma unroll
        for (int p = 0; p < 4; p++) acc[j][p] = 0ull;

    gemm_chunked((const float4*)(Wqkv + (size_t)257 * 256), Xs, Wc, acc, tid, c0, w0);

    __syncthreads();  // all V-GEMM reads of Xs done before overwriting with g
    #pragma unroll
    for (int j = 0; j < 8; j++) {
        int c = c0 + j;
        float bv = __ldg(&bqkv[257 + c]);
        float cv = cv_s[c];
        unsigned long long* grow = (unsigned long long*)&Xs[c * XS_STRIDE + w0];
        #pragma unroll
        for (int p = 0; p < 4; p++) {
            float lo, hi;
            unpack2(acc[j][p], lo, hi);
            lo = fmaxf(lo + bv, 0.f) * cv;
            hi = fmaxf(hi + bv, 0.f) * cv;
            grow[p] = pack2(lo, hi);
        }
    }
    // first __syncthreads inside gemm_chunked makes g-writes visible

    // ================= Out GEMM: out = Wout.g + bout =================
    #pragma unroll
    for (int j = 0; j < 8; j++)
        #pragma unroll
        for (int p = 0; p < 4; p++) acc[j][p] = 0ull;

    gemm_chunked((const float4*)Wout, Xs, Wc, acc, tid, c0, w0);

    float* obase = out + (size_t)b * 256 * 4096 + (size_t)h * 64;
    #pragma unroll
    for (int j = 0; j < 8; j++) {
        int o = c0 + j;
        float bo = __ldg(&bout[o]);
        float l0, h0, l1, h1, l2, h2, l3, h3;
        unpack2(acc[j][0], l0, h0);
        unpack2(acc[j][1], l1, h1);
        unpack2(acc[j][2], l2, h2);
        unpack2(acc[j][3], l3, h3);
        float4 r0 = make_float4(l0 + bo, h0 + bo, l1 + bo, h1 + bo);
        float4 r1 = make_float4(l2 + bo, h2 + bo, l3 + bo, h3 + bo);
        *(float4*)&obase[(size_t)o * 4096 + w0]     = r0;
        *(float4*)&obase[(size_t)o * 4096 + w0 + 4] = r1;
    }
}

extern "C" void kernel_launch(void* const* d_in, const int* in_sizes, int n_in,
                              void* d_out, int out_size)
{
    const float* x    = (const float*)d_in[0];
    const float* Wqkv = (const float*)d_in[1];
    const float* bqkv = (const float*)d_in[2];
    const float* Wout = (const float*)d_in[3];
    const float* bout = (const float*)d_in[4];
    float* out = (float*)d_out;

    const int smem_bytes = SMEM_FLOATS * sizeof(float);  // ~107 KB
    cudaFuncSetAttribute(sepattn_kernel,
                         cudaFuncAttributeMaxDynamicSharedMemorySize, smem_bytes);

    sepattn_kernel<<<2048, 256, smem_bytes>>>(x, Wqkv, bqkv, Wout, bout, out);
}

// round 5
// speedup vs baseline: 1.0006x; 1.0006x over previous
#include <cuda_runtime.h>
#include <cstdint>
#include <cstdio>

// SeparableAttention fused kernel (exact fp32, packed f32x2 FMA path).
//
// Math (per (b,h) tile, X = x[b,:,h,:] of shape [256 c][64 w]):
//   q[w]  = Wq.X[:,w] + bq         (Wq = Wqkv row 0)
//   s     = softmax(q)             (over w, sums to 1)
//   xs[c] = sum_w X[c,w] s[w]
//   cv[c] = Wk[c,:].xs + bk[c]     (K-GEMM eliminated since sum(s)=1)
//   v     = Wv.X + bv ; g = relu(v) * cv[c]
//   out   = Wout.g + bout
//
// Grid: 2048 blocks = (b,h); Block: 256 threads; each thread owns an
// 8c x 8w register tile (32 packed f32x2 accumulators).

#define XS_STRIDE 68    // 64 + 4 pad: float4-aligned rows
#define WC_STRIDE 265   // 256 + 9 pad: conflict-free chunk store & read

#define SMEM_FLOATS (256 * XS_STRIDE + 32 * WC_STRIDE + 256 + 64 + 64 + 256 + 256 + 4)

__device__ __forceinline__ unsigned long long bcast2(float w) {
    unsigned long long r;
    asm("mov.b64 %0, {%1, %1};" : "=l"(r) : "f"(w));
    return r;
}
__device__ __forceinline__ void ffma2(unsigned long long& d, unsigned long long a,
                                      unsigned long long b) {
    asm("fma.rn.f32x2 %0, %1, %2, %0;" : "+l"(d) : "l"(a), "l"(b));
}
__device__ __forceinline__ void unpack2(unsigned long long v, float& lo, float& hi) {
    asm("mov.b64 {%0, %1}, %2;" : "=f"(lo), "=f"(hi) : "l"(v));
}
__device__ __forceinline__ unsigned long long pack2(float lo, float hi) {
    unsigned long long r;
    asm("mov.b64 %0, {%1, %2};" : "=l"(r) : "f"(lo), "f"(hi));
    return r;
}

// One chunked 256x64x256 GEMM: acc[j][p] (+)= W[c0+j, e] * X[e, w0 + 2p..2p+1]
// Wg4: global weight base, element (r, e) at float index r*256 + e.
__device__ __forceinline__ void gemm_chunked(const float4* __restrict__ Wg4,
                                             const float* Xs, float* Wc,
                                             unsigned long long acc[8][4],
                                             int tid, int c0, int w0)
{
    for (int kc = 0; kc < 8; kc++) {
        __syncthreads();  // previous chunk consumed (or Xs/g writes visible)
        #pragma unroll
        for (int k = 0; k < 8; k++) {
            int idx = tid + k * 256;
            int e4 = idx & 7;         // which float4 within the 32-wide chunk
            int r  = idx >> 3;        // weight row (output channel)
            float4 v = __ldg(&Wg4[r * 64 + kc * 8 + e4]);
            int el = 4 * e4;
            Wc[(el + 0) * WC_STRIDE + r] = v.x;
            Wc[(el + 1) * WC_STRIDE + r] = v.y;
            Wc[(el + 2) * WC_STRIDE + r] = v.z;
            Wc[(el + 3) * WC_STRIDE + r] = v.w;
        }
        __syncthreads();
        #pragma unroll 8
        for (int el = 0; el < 32; el++) {
            int e = kc * 32 + el;
            const unsigned long long* xr =
                (const unsigned long long*)&Xs[e * XS_STRIDE + w0];
            unsigned long long xp0 = xr[0], xp1 = xr[1], xp2 = xr[2], xp3 = xr[3];
            const float* wrow = &Wc[el * WC_STRIDE + c0];
            #pragma unroll
            for (int j = 0; j < 8; j++) {
                unsigned long long wp = bcast2(wrow[j]);
                ffma2(acc[j][0], wp, xp0);
                ffma2(acc[j][1], wp, xp1);
                ffma2(acc[j][2], wp, xp2);
                ffma2(acc[j][3], wp, xp3);
            }
        }
    }
}

__global__ __launch_bounds__(256, 2)
void sepattn_kernel(const float* __restrict__ x,
                    const float* __restrict__ Wqkv,
                    const float* __restrict__ bqkv,
                    const float* __restrict__ Wout,
                    const float* __restrict__ bout,
                    float* __restrict__ out)
{
    extern __shared__ float smem[];
    float* Xs   = smem;                        // 256*68  (X tile, later g tile)
    float* Wc   = Xs   + 256 * XS_STRIDE;      // 32*265  (weight K-chunk, [el][r])
    float* Wq_s = Wc   + 32 * WC_STRIDE;       // 256
    float* q_s  = Wq_s + 256;                  // 64
    float* s_s  = q_s  + 64;                   // 64
    float* xs_s = s_s  + 64;                   // 256
    float* cv_s = xs_s + 256;                  // 256
    float* red  = cv_s + 256;                  // 2

    const int tid = threadIdx.x;
    const int b = blockIdx.x >> 6;
    const int h = blockIdx.x & 63;

    // ---- load X tile (256 c x 64 w) into smem ----
    const float4* x4 = (const float4*)(x + (size_t)b * 256 * 4096 + (size_t)h * 64);
    #pragma unroll
    for (int k = 0; k < 16; k++) {
        int idx = tid + k * 256;
        int w4 = idx & 15, c = idx >> 4;
        float4 v = __ldg(&x4[c * 1024 + w4]);
        *(float4*)&Xs[c * XS_STRIDE + 4 * w4] = v;
    }
    if (tid < 64) {  // stage Wq (row 0 of Wqkv)
        float4 v = __ldg(&((const float4*)Wqkv)[tid]);
        *(float4*)&Wq_s[4 * tid] = v;
    }
    __syncthreads();

    // ---- q[w] = Wq . X[:,w] + bq ----
    if (tid < 64) {
        float acc = __ldg(&bqkv[0]);
        #pragma unroll 8
        for (int c = 0; c < 256; c++)
            acc = fmaf(Wq_s[c], Xs[c * XS_STRIDE + tid], acc);
        q_s[tid] = acc;
    }
    __syncthreads();
    // ---- softmax over 64 ----
    if (tid < 32) {
        float m = fmaxf(q_s[tid], q_s[tid + 32]);
        #pragma unroll
        for (int o = 16; o > 0; o >>= 1) m = fmaxf(m, __shfl_xor_sync(0xffffffffu, m, o));
        if (tid == 0) red[0] = m;
    }
    __syncthreads();
    if (tid < 64) q_s[tid] = __expf(q_s[tid] - red[0]);
    __syncthreads();
    if (tid < 32) {
        float s = q_s[tid] + q_s[tid + 32];
        #pragma unroll
        for (int o = 16; o > 0; o >>= 1) s += __shfl_xor_sync(0xffffffffu, s, o);
        if (tid == 0) red[1] = 1.0f / s;
    }
    __syncthreads();
    if (tid < 64) s_s[tid] = q_s[tid] * red[1];
    __syncthreads();

    // ---- xs[c] = sum_w X[c,w] * s[w] ----
    {
        float acc = 0.f;
        #pragma unroll 8
        for (int w = 0; w < 64; w++)
            acc = fmaf(Xs[tid * XS_STRIDE + w], s_s[w], acc);
        xs_s[tid] = acc;
    }
    __syncthreads();
    // ---- cv[c] = Wk[c,:] . xs + bk[c]   (Wk = Wqkv rows 1..256) ----
    {
        const float4* wk4 = (const float4*)(Wqkv + (size_t)(1 + tid) * 256);
        const float4* xs4 = (const float4*)xs_s;
        float acc = __ldg(&bqkv[1 + tid]);
        #pragma unroll 8
        for (int j = 0; j < 64; j++) {
            float4 wv = __ldg(&wk4[j]);
            float4 xv = xs4[j];
            acc += wv.x * xv.x + wv.y * xv.y + wv.z * xv.z + wv.w * xv.w;
        }
        cv_s[tid] = acc;
    }
    // (gemm_chunked begins with __syncthreads — covers cv_s visibility)

    const int c0 = (tid >> 3) * 8;
    const int w0 = (tid & 7) * 8;
    unsigned long long acc[8][4];

    // ================= V GEMM: v = Wv.X (+bv) =================
    #pragma unroll
    for (int j = 0; j < 8; j++)
        #pragma unroll
        for (int p = 0; p < 4; p++) acc[j][p] = 0ull;

    gemm_chunked((const float4*)(Wqkv + (size_t)257 * 256), Xs, Wc, acc, tid, c0, w0);

    __syncthreads();  // all V-GEMM reads of Xs done before overwriting with g
    #pragma unroll
    for (int j = 0; j < 8; j++) {
        int c = c0 + j;
        float bv = __ldg(&bqkv[257 + c]);
        float cv = cv_s[c];
        unsigned long long* grow = (unsigned long long*)&Xs[c * XS_STRIDE + w0];
        #pragma unroll
        for (int p = 0; p < 4; p++) {
            float lo, hi;
            unpack2(acc[j][p], lo, hi);
            lo = fmaxf(lo + bv, 0.f) * cv;
            hi = fmaxf(hi + bv, 0.f) * cv;
            grow[p] = pack2(lo, hi);
        }
    }
    // first __syncthreads inside gemm_chunked makes g-writes visible

    // ================= Out GEMM: out = Wout.g + bout =================
    #pragma unroll
    for (int j = 0; j < 8; j++)
        #pragma unroll
        for (int p = 0; p < 4; p++) acc[j][p] = 0ull;

    gemm_chunked((const float4*)Wout, Xs, Wc, acc, tid, c0, w0);

    float* obase = out + (size_t)b * 256 * 4096 + (size_t)h * 64;
    #pragma unroll
    for (int j = 0; j < 8; j++) {
        int o = c0 + j;
        float bo = __ldg(&bout[o]);
        float l0, h0, l1, h1, l2, h2, l3, h3;
        unpack2(acc[j][0], l0, h0);
        unpack2(acc[j][1], l1, h1);
        unpack2(acc[j][2], l2, h2);
        unpack2(acc[j][3], l3, h3);
        float4 r0 = make_float4(l0 + bo, h0 + bo, l1 + bo, h1 + bo);
        float4 r1 = make_float4(l2 + bo, h2 + bo, l3 + bo, h3 + bo);
        *(float4*)&obase[(size_t)o * 4096 + w0]     = r0;
        *(float4*)&obase[(size_t)o * 4096 + w0 + 4] = r1;
    }
}

extern "C" void kernel_launch(void* const* d_in, const int* in_sizes, int n_in,
                              void* d_out, int out_size)
{
    const float* x    = (const float*)d_in[0];
    const float* Wqkv = (const float*)d_in[1];
    const float* bqkv = (const float*)d_in[2];
    const float* Wout = (const float*)d_in[3];
    const float* bout = (const float*)d_in[4];
    float* out = (float*)d_out;

    const int smem_bytes = SMEM_FLOATS * sizeof(float);  // ~107 KB
    cudaFuncSetAttribute(sepattn_kernel,
                         cudaFuncAttributeMaxDynamicSharedMemorySize, smem_bytes);

    sepattn_kernel<<<2048, 256, smem_bytes>>>(x, Wqkv, bqkv, Wout, bout, out);
}

// round 8
// speedup vs baseline: 1.6019x; 1.6010x over previous
#include <cuda_runtime.h>
#include <cuda_bf16.h>
#include <cstdint>

// ============================================================================
// SeparableAttention — fused single kernel, tensor cores via mma.sync bf16
// (3-term hi/lo split, exact fp32 softmax path). PTX target sm_103-safe:
// no tcgen05, only ldmatrix + mma.sync (sm_80+ baseline features).
//
// Per (b,h) block (2048 blocks, 256 thr):
//   phase1: q = Wq.X + bq; s = softmax(q); xs = X.s; cv = Wk.xs + bk   (fp32)
//   conv:   X (fp32 smem) -> Xh/Xl bf16 smem tiles [c=256][w=64]
//   GEMM1:  V = Wv.X   (A chunks streamed from L2, double-buffered)
//   epi1:   g = relu(v+bv)*cv -> overwrite Xh/Xl with G
//   GEMM2:  OUT = Wout.G ; epi2: +bout -> global out
// ============================================================================

#define XSS 66
#define OFF_XS   0                       // fp32 X tile 256*66*4 = 67584
#define OFF_XH   67584                   // bf16 hi tile 256*72*2 = 36864 (alias: Wks)
#define OFF_XL   104448                  // bf16 lo tile 36864
#define OFF_AB   141312                  // A chunk buffers: 4 * 12288 = 49152
#define AB_HALF  12288                   // lo-part offset inside a buffer pair
#define AB_PAIR  24576                   // stride between double buffers
#define OFF_TAIL 190464                  // small fp32 arrays
#define SMEM_BYTES (OFF_TAIL + 4096)     // 194560 B

// ---------------------------- helpers ---------------------------------------
__device__ __forceinline__ uint32_t smem_u32(const void* p) {
    uint32_t a;
    asm("{ .reg .u64 t; cvta.to.shared.u64 t, %1; cvt.u32.u64 %0, t; }"
        : "=r"(a) : "l"(p));
    return a;
}
__device__ __forceinline__ uint32_t pack2bf(float a, float b) {
    __nv_bfloat162 t = __floats2bfloat162_rn(a, b);
    return *reinterpret_cast<uint32_t*>(&t);
}
__device__ __forceinline__ float bf_hi(float v) {
    return __bfloat162float(__float2bfloat16(v));
}

#define LDM4(r0, r1, r2, r3, a) \
    asm volatile("ldmatrix.sync.aligned.m8n8.x4.shared.b16 {%0,%1,%2,%3}, [%4];" \
        : "=r"(r0), "=r"(r1), "=r"(r2), "=r"(r3) : "r"(a))
#define LDM4T(r0, r1, r2, r3, a) \
    asm volatile("ldmatrix.sync.aligned.m8n8.x4.trans.shared.b16 {%0,%1,%2,%3}, [%4];" \
        : "=r"(r0), "=r"(r1), "=r"(r2), "=r"(r3) : "r"(a))
#define MMA16816(d, a, b) \
    asm volatile("mma.sync.aligned.m16n8k16.row.col.f32.bf16.bf16.f32 " \
        "{%0,%1,%2,%3}, {%4,%5,%6,%7}, {%8,%9}, {%0,%1,%2,%3};" \
        : "+f"((d)[0]), "+f"((d)[1]), "+f"((d)[2]), "+f"((d)[3]) \
        : "r"((a)[0]), "r"((a)[1]), "r"((a)[2]), "r"((a)[3]), \
          "r"((b)[0]), "r"((b)[1]))

// Store one converted A chunk (256 m x 16 k, hi+lo) into buffer p.
__device__ __forceinline__ void sts_chunk(char* smc, int p, const float4* rg,
                                          int tid) {
    #pragma unroll
    for (int i = 0; i < 4; i++) {
        int idx = tid + i * 256;
        int r = idx >> 2, q = idx & 3;
        float4 v = rg[i];
        float hx = bf_hi(v.x), hy = bf_hi(v.y), hz = bf_hi(v.z), hw = bf_hi(v.w);
        uint32_t h01 = pack2bf(hx, hy), h23 = pack2bf(hz, hw);
        uint32_t l01 = pack2bf(v.x - hx, v.y - hy);
        uint32_t l23 = pack2bf(v.z - hz, v.w - hw);
        char* base = smc + OFF_AB + p * AB_PAIR + r * 48 + q * 8;
        *(uint2*)base = make_uint2(h01, h23);
        *(uint2*)(base + AB_HALF) = make_uint2(l01, l23);
    }
}

// Main loop of one 256x64x256 GEMM (3-term bf16 split), B resident in Xh/Xl.
__device__ __forceinline__ void gemm_main(const float4* __restrict__ W4,
                                          char* smc, uint32_t smb,
                                          float acc[2][8][4], int tid) {
    const int lane = tid & 31, wid = tid >> 5;
    const int warp_m = wid * 32;
    const int lrow = (lane & 7) + ((lane >> 3) & 1) * 8;   // 0..15
    const int lcol = (lane >> 4) * 8;                      // 0 or 8

    float4 rg[4];
    #pragma unroll
    for (int i = 0; i < 4; i++) {                          // chunk 0
        int idx = tid + i * 256; int r = idx >> 2, q = idx & 3;
        rg[i] = __ldg(&W4[r * 64 + q]);
    }
    sts_chunk(smc, 0, rg, tid);
    #pragma unroll
    for (int i = 0; i < 4; i++) {                          // chunk 1 -> regs
        int idx = tid + i * 256; int r = idx >> 2, q = idx & 3;
        rg[i] = __ldg(&W4[r * 64 + 4 + q]);
    }
    __syncthreads();

    #pragma unroll 2
    for (int ks = 0; ks < 16; ks++) {
        const int p = ks & 1;
        uint32_t Ah[2][4], Al[2][4], Bh[8][2], Bl[8][2];
        #pragma unroll
        for (int mf = 0; mf < 2; mf++) {
            uint32_t abase = smb + OFF_AB + p * AB_PAIR +
                ((uint32_t)(warp_m + 16 * mf + lrow) * 24 + lcol) * 2;
            LDM4(Ah[mf][0], Ah[mf][1], Ah[mf][2], Ah[mf][3], abase);
            LDM4(Al[mf][0], Al[mf][1], Al[mf][2], Al[mf][3], abase + AB_HALF);
        }
        const int k0 = ks * 16;
        #pragma unroll
        for (int nn = 0; nn < 4; nn++) {
            uint32_t boff = ((uint32_t)(k0 + lrow) * 72 + nn * 16 + lcol) * 2;
            uint32_t t0, t1, t2, t3;
            LDM4T(t0, t1, t2, t3, smb + OFF_XH + boff);
            Bh[2*nn][0] = t0; Bh[2*nn][1] = t1;
            Bh[2*nn+1][0] = t2; Bh[2*nn+1][1] = t3;
            LDM4T(t0, t1, t2, t3, smb + OFF_XL + boff);
            Bl[2*nn][0] = t0; Bl[2*nn][1] = t1;
            Bl[2*nn+1][0] = t2; Bl[2*nn+1][1] = t3;
        }
        #pragma unroll
        for (int mf = 0; mf < 2; mf++)
            #pragma unroll
            for (int nf = 0; nf < 8; nf++) {
                MMA16816(acc[mf][nf], Ah[mf], Bh[nf]);
                MMA16816(acc[mf][nf], Ah[mf], Bl[nf]);
                MMA16816(acc[mf][nf], Al[mf], Bh[nf]);
            }
        if (ks < 15) {
            __syncthreads();                 // prev readers of buf[1-p] done
            sts_chunk(smc, (ks + 1) & 1, rg, tid);
            if (ks < 14) {
                #pragma unroll
                for (int i = 0; i < 4; i++) {
                    int idx = tid + i * 256; int r = idx >> 2, q = idx & 3;
                    rg[i] = __ldg(&W4[r * 64 + (ks + 2) * 4 + q]);
                }
            }
            __syncthreads();                 // STS visible for next kstep
        }
    }
}

// ============================================================================
__global__ __launch_bounds__(256, 1)
void sepattn_tc(const float* __restrict__ x,
                const float* __restrict__ Wqkv,
                const float* __restrict__ bqkv,
                const float* __restrict__ Wout,
                const float* __restrict__ bout,
                float* __restrict__ out)
{
    extern __shared__ char smc[];
    float* Xs   = (float*)(smc + OFF_XS);
    float* Wks  = (float*)(smc + OFF_XH);      // phase-1 alias of Xh region
    float* tail = (float*)(smc + OFF_TAIL);
    float* cv_s = tail;                        // 256
    float* q_s  = tail + 256;                  // 64
    float* s_s  = tail + 320;                  // 64
    float* xs_s = tail + 384;                  // 256
    float* Wq_s = tail + 640;                  // 256
    float* red  = tail + 896;                  // 8
    const uint32_t smb = smem_u32(smc);

    const int tid = threadIdx.x;
    const int lane = tid & 31, wid = tid >> 5;
    const int b = blockIdx.x >> 6;
    const int h = blockIdx.x & 63;

    // ---------------- phase 0: load X tile [256 c][64 w] --------------------
    const float2* x2 = (const float2*)(x + (size_t)b * 256 * 4096);
    #pragma unroll
    for (int k = 0; k < 32; k++) {
        int idx = tid + k * 256;
        int w2 = idx & 31, c = idx >> 5;
        float2 v = __ldg(&x2[c * 2048 + h * 32 + w2]);
        *(float2*)&Xs[c * XSS + 2 * w2] = v;
    }
    if (tid < 64) {
        float4 v = __ldg(&((const float4*)Wqkv)[tid]);
        *(float4*)&Wq_s[4 * tid] = v;
    }
    __syncthreads();

    // ---------------- phase 1: q, softmax, xs, cv (fp32 exact) --------------
    if (tid < 64) {
        float a = __ldg(&bqkv[0]);
        #pragma unroll 8
        for (int c = 0; c < 256; c++)
            a = fmaf(Wq_s[c], Xs[c * XSS + tid], a);
        q_s[tid] = a;
    }
    __syncthreads();
    if (tid < 32) {
        float m = fmaxf(q_s[tid], q_s[tid + 32]);
        #pragma unroll
        for (int o = 16; o > 0; o >>= 1)
            m = fmaxf(m, __shfl_xor_sync(0xffffffffu, m, o));
        if (tid == 0) red[0] = m;
    }
    __syncthreads();
    if (tid < 64) q_s[tid] = __expf(q_s[tid] - red[0]);
    __syncthreads();
    if (tid < 32) {
        float s = q_s[tid] + q_s[tid + 32];
        #pragma unroll
        for (int o = 16; o > 0; o >>= 1) s += __shfl_xor_sync(0xffffffffu, s, o);
        if (tid == 0) red[1] = 1.0f / s;
    }
    __syncthreads();
    if (tid < 64) s_s[tid] = q_s[tid] * red[1];
    __syncthreads();

    {   // xs[c] = sum_w X[c,w] s[w]
        float a = 0.f;
        #pragma unroll 8
        for (int w = 0; w < 64; w++)
            a = fmaf(Xs[tid * XSS + w], s_s[w], a);
        xs_s[tid] = a;
    }

    // cv[c] = Wk[c,:].xs + bk[c], staged through Wks (stride 36)
    float acc_cv = __ldg(&bqkv[1 + tid]);
    const float4* W4full = (const float4*)Wqkv;
    for (int ec = 0; ec < 8; ec++) {
        __syncthreads();
        #pragma unroll
        for (int i = 0; i < 8; i++) {
            int idx = tid + i * 256;
            int r = idx >> 3, q = idx & 7;
            float4 v = __ldg(&W4full[(size_t)(1 + r) * 64 + ec * 8 + q]);
            *(float4*)&Wks[r * 36 + q * 4] = v;
        }
        __syncthreads();
        #pragma unroll 8
        for (int e = 0; e < 32; e++) {
            int er = (e + tid) & 31;
            acc_cv = fmaf(Wks[tid * 36 + er], xs_s[ec * 32 + er], acc_cv);
        }
    }
    cv_s[tid] = acc_cv;
    __syncthreads();            // all Wks reads done before Xh overwrite

    // ---------------- convert X -> Xh/Xl bf16 tiles -------------------------
    #pragma unroll 4
    for (int w = 0; w < 64; w += 2) {
        float v0 = Xs[tid * XSS + w], v1 = Xs[tid * XSS + w + 1];
        float h0 = bf_hi(v0), h1 = bf_hi(v1);
        uint32_t off = ((uint32_t)tid * 72 + w) * 2;
        *(uint32_t*)(smc + OFF_XH + off) = pack2bf(h0, h1);
        *(uint32_t*)(smc + OFF_XL + off) = pack2bf(v0 - h0, v1 - h1);
    }
    // gemm_main's prologue __syncthreads orders these stores

    float acc[2][8][4];
    #pragma unroll
    for (int i = 0; i < 2; i++)
        #pragma unroll
        for (int j = 0; j < 8; j++)
            #pragma unroll
            for (int k = 0; k < 4; k++) acc[i][j][k] = 0.f;

    // ================= GEMM1: V = Wv . X =================
    gemm_main((const float4*)(Wqkv + (size_t)257 * 256), smc, smb, acc, tid);

    __syncthreads();            // all B reads done before overwriting with G
    {   // epi1: g = relu(v+bv)*cv -> Xh/Xl
        const int rb = wid * 32 + (lane >> 2);
        const int cb = 2 * (lane & 3);
        #pragma unroll
        for (int mf = 0; mf < 2; mf++)
            #pragma unroll
            for (int hf = 0; hf < 2; hf++) {
                int r = rb + 16 * mf + 8 * hf;
                float bv = __ldg(&bqkv[257 + r]);
                float cv = cv_s[r];
                #pragma unroll
                for (int nf = 0; nf < 8; nf++) {
                    float g0 = fmaxf(acc[mf][nf][2 * hf + 0] + bv, 0.f) * cv;
                    float g1 = fmaxf(acc[mf][nf][2 * hf + 1] + bv, 0.f) * cv;
                    float h0 = bf_hi(g0), h1 = bf_hi(g1);
                    uint32_t off = ((uint32_t)r * 72 + 8 * nf + cb) * 2;
                    *(uint32_t*)(smc + OFF_XH + off) = pack2bf(h0, h1);
                    *(uint32_t*)(smc + OFF_XL + off) = pack2bf(g0 - h0, g1 - h1);
                }
            }
    }

    #pragma unroll
    for (int i = 0; i < 2; i++)
        #pragma unroll
        for (int j = 0; j < 8; j++)
            #pragma unroll
            for (int k = 0; k < 4; k++) acc[i][j][k] = 0.f;

    // ================= GEMM2: OUT = Wout . G =================
    gemm_main((const float4*)Wout, smc, smb, acc, tid);

    {   // epi2: + bout -> global out
        float* ob = out + (size_t)b * 1048576 + (size_t)h * 64;
        const int rb = wid * 32 + (lane >> 2);
        const int cb = 2 * (lane & 3);
        #pragma unroll
        for (int mf = 0; mf < 2; mf++)
            #pragma unroll
            for (int hf = 0; hf < 2; hf++) {
                int r = rb + 16 * mf + 8 * hf;
                float bo = __ldg(&bout[r]);
                #pragma unroll
                for (int nf = 0; nf < 8; nf++) {
                    float2 v;
                    v.x = acc[mf][nf][2 * hf + 0] + bo;
                    v.y = acc[mf][nf][2 * hf + 1] + bo;
                    *(float2*)(ob + (size_t)r * 4096 + 8 * nf + cb) = v;
                }
            }
    }
}

// ============================================================================
extern "C" void kernel_launch(void* const* d_in, const int* in_sizes, int n_in,
                              void* d_out, int out_size)
{
    const float* x    = (const float*)d_in[0];
    const float* Wqkv = (const float*)d_in[1];
    const float* bqkv = (const float*)d_in[2];
    const float* Wout = (const float*)d_in[3];
    const float* bout = (const float*)d_in[4];
    float* out = (float*)d_out;

    cudaFuncSetAttribute(sepattn_tc,
                         cudaFuncAttributeMaxDynamicSharedMemorySize, SMEM_BYTES);
    sepattn_tc<<<2048, 256, SMEM_BYTES>>>(x, Wqkv, bqkv, Wout, bout, out);
}

// round 9
// speedup vs baseline: 2.4032x; 1.5002x over previous
#include <cuda_runtime.h>
#include <cuda_fp16.h>
#include <cstdint>

// ============================================================================
// SeparableAttention — fused, mma.sync fp16 2-term split (W = hi+lo fp16,
// X/G = fp16 hi), fp32-exact softmax path via X = Xh + Xl reconstruction.
// 92KB smem -> 2 CTAs/SM; PTX sm_103-safe (no tcgen05).
//
// smem layout (per CTA):
//   [OFF_XH ) Xh fp16 [256][72]                     36864 B  (GEMM B operand)
//   [OFF_SCR) scratch 49152 B, time-multiplexed:
//       phase1a: Xl fp16 [256][72]  (36864)
//       phase1b: Wks fp32 [256][36] (36864)
//       gemms:   A chunks, double-buffered hi+lo (2 x 24576)
//   [OFF_TAIL) fp32 tail arrays (cv, q, s, xs, Wq, qp, red)
// ============================================================================

#define OFF_XH   0
#define OFF_SCR  36864
#define AB_HALF  12288
#define AB_PAIR  24576
#define OFF_TAIL 86016
#define SMEM_BYTES (OFF_TAIL + 8192)      // 94208 B

// ---------------------------- helpers ---------------------------------------
__device__ __forceinline__ uint32_t smem_u32(const void* p) {
    uint32_t a;
    asm("{ .reg .u64 t; cvta.to.shared.u64 t, %1; cvt.u32.u64 %0, t; }"
        : "=r"(a) : "l"(p));
    return a;
}
__device__ __forceinline__ uint32_t pack2h(float a, float b) {
    __half2 t = __floats2half2_rn(a, b);
    return *reinterpret_cast<uint32_t*>(&t);
}
__device__ __forceinline__ float h_hi(float v) {
    return __half2float(__float2half_rn(v));
}

#define LDM4(r0, r1, r2, r3, a) \
    asm volatile("ldmatrix.sync.aligned.m8n8.x4.shared.b16 {%0,%1,%2,%3}, [%4];" \
        : "=r"(r0), "=r"(r1), "=r"(r2), "=r"(r3) : "r"(a))
#define LDM4T(r0, r1, r2, r3, a) \
    asm volatile("ldmatrix.sync.aligned.m8n8.x4.trans.shared.b16 {%0,%1,%2,%3}, [%4];" \
        : "=r"(r0), "=r"(r1), "=r"(r2), "=r"(r3) : "r"(a))
#define MMA16816(d, a, b) \
    asm volatile("mma.sync.aligned.m16n8k16.row.col.f32.f16.f16.f32 " \
        "{%0,%1,%2,%3}, {%4,%5,%6,%7}, {%8,%9}, {%0,%1,%2,%3};" \
        : "+f"((d)[0]), "+f"((d)[1]), "+f"((d)[2]), "+f"((d)[3]) \
        : "r"((a)[0]), "r"((a)[1]), "r"((a)[2]), "r"((a)[3]), \
          "r"((b)[0]), "r"((b)[1]))

// Store one converted A chunk (256 m x 16 k, fp16 hi+lo) into buffer p.
__device__ __forceinline__ void sts_chunk(char* smc, int p, const float4* rg,
                                          int tid) {
    #pragma unroll
    for (int i = 0; i < 4; i++) {
        int idx = tid + i * 256;
        int r = idx >> 2, q = idx & 3;
        float4 v = rg[i];
        float hx = h_hi(v.x), hy = h_hi(v.y), hz = h_hi(v.z), hw = h_hi(v.w);
        char* base = smc + OFF_SCR + p * AB_PAIR + r * 48 + q * 8;
        *(uint2*)base = make_uint2(pack2h(hx, hy), pack2h(hz, hw));
        *(uint2*)(base + AB_HALF) =
            make_uint2(pack2h(v.x - hx, v.y - hy), pack2h(v.z - hz, v.w - hw));
    }
}

// One 256x64x256 GEMM main loop, 2-term fp16 split; B = Xh resident tile.
__device__ __forceinline__ void gemm_main(const float4* __restrict__ W4,
                                          char* smc, uint32_t smb,
                                          float acc[2][8][4], int tid) {
    const int lane = tid & 31, wid = tid >> 5;
    const int warp_m = wid * 32;
    const int lrow = (lane & 7) + ((lane >> 3) & 1) * 8;   // 0..15
    const int lcol = (lane >> 4) * 8;                      // 0 or 8

    float4 rg[4];
    #pragma unroll
    for (int i = 0; i < 4; i++) {                          // chunk 0
        int idx = tid + i * 256; int r = idx >> 2, q = idx & 3;
        rg[i] = __ldg(&W4[r * 64 + q]);
    }
    sts_chunk(smc, 0, rg, tid);
    #pragma unroll
    for (int i = 0; i < 4; i++) {                          // chunk 1 -> regs
        int idx = tid + i * 256; int r = idx >> 2, q = idx & 3;
        rg[i] = __ldg(&W4[r * 64 + 4 + q]);
    }
    __syncthreads();

    #pragma unroll 2
    for (int ks = 0; ks < 16; ks++) {
        const int p = ks & 1;
        uint32_t Ah[2][4], Al[2][4], Bh[8][2];
        #pragma unroll
        for (int mf = 0; mf < 2; mf++) {
            uint32_t abase = smb + OFF_SCR + p * AB_PAIR +
                (uint32_t)(warp_m + 16 * mf + lrow) * 48 + lcol * 2;
            LDM4(Ah[mf][0], Ah[mf][1], Ah[mf][2], Ah[mf][3], abase);
            LDM4(Al[mf][0], Al[mf][1], Al[mf][2], Al[mf][3], abase + AB_HALF);
        }
        const int k0 = ks * 16;
        #pragma unroll
        for (int nn = 0; nn < 4; nn++) {
            uint32_t boff = (uint32_t)(k0 + lrow) * 144 + (nn * 16 + lcol) * 2;
            uint32_t t0, t1, t2, t3;
            LDM4T(t0, t1, t2, t3, smb + OFF_XH + boff);
            Bh[2 * nn][0] = t0;     Bh[2 * nn][1] = t1;
            Bh[2 * nn + 1][0] = t2; Bh[2 * nn + 1][1] = t3;
        }
        #pragma unroll
        for (int mf = 0; mf < 2; mf++)
            #pragma unroll
            for (int nf = 0; nf < 8; nf++) {
                MMA16816(acc[mf][nf], Ah[mf], Bh[nf]);
                MMA16816(acc[mf][nf], Al[mf], Bh[nf]);
            }
        if (ks < 15) {
            __syncthreads();                 // readers of buf[1-p] done
            sts_chunk(smc, (ks + 1) & 1, rg, tid);
            if (ks < 14) {
                #pragma unroll
                for (int i = 0; i < 4; i++) {
                    int idx = tid + i * 256; int r = idx >> 2, q = idx & 3;
                    rg[i] = __ldg(&W4[r * 64 + (ks + 2) * 4 + q]);
                }
            }
            __syncthreads();                 // STS visible for next kstep
        }
    }
}

// ============================================================================
__global__ __launch_bounds__(256, 2)
void sepattn_tc(const float* __restrict__ x,
                const float* __restrict__ Wqkv,
                const float* __restrict__ bqkv,
                const float* __restrict__ Wout,
                const float* __restrict__ bout,
                float* __restrict__ out)
{
    extern __shared__ char smc[];
    float* tail = (float*)(smc + OFF_TAIL);
    float* cv_s = tail;                        // 256
    float* q_s  = tail + 256;                  // 64
    float* s_s  = tail + 320;                  // 64
    float* xs_s = tail + 384;                  // 256
    float* Wq_s = tail + 640;                  // 256
    float* qp   = tail + 896;                  // 256 (q partials)
    float* red  = tail + 1152;                 // 8
    float* Wks  = (float*)(smc + OFF_SCR);     // phase-1b alias
    const uint32_t smb = smem_u32(smc);

    const int tid = threadIdx.x;
    const int lane = tid & 31, wid = tid >> 5;
    const int b = blockIdx.x >> 6;
    const int h = blockIdx.x & 63;

    // -------- phase 0: load X tile, split to Xh (fp16) + Xl (fp16) ----------
    const float2* x2 = (const float2*)(x + (size_t)b * 256 * 4096);
    #pragma unroll
    for (int k = 0; k < 32; k++) {
        int idx = tid + k * 256;
        int w2 = idx & 31, c = idx >> 5;
        float2 v = __ldg(&x2[c * 2048 + h * 32 + w2]);
        float h0 = h_hi(v.x), h1 = h_hi(v.y);
        uint32_t off = ((uint32_t)c * 72 + 2 * w2) * 2;
        *(uint32_t*)(smc + OFF_XH + off) = pack2h(h0, h1);
        *(uint32_t*)(smc + OFF_SCR + off) = pack2h(v.x - h0, v.y - h1);
    }
    if (tid < 64) {
        float4 v = __ldg(&((const float4*)Wqkv)[tid]);
        *(float4*)&Wq_s[4 * tid] = v;
    }
    __syncthreads();

    // -------- phase 1: q (all 256 threads), softmax, xs, cv -----------------
    {
        int w = tid & 63, part = tid >> 6;
        const __half* XH = (const __half*)(smc + OFF_XH);
        const __half* XL = (const __half*)(smc + OFF_SCR);
        float a = 0.f;
        #pragma unroll 8
        for (int c = part * 64; c < part * 64 + 64; c++)
            a = fmaf(Wq_s[c],
                     __half2float(XH[c * 72 + w]) + __half2float(XL[c * 72 + w]),
                     a);
        qp[part * 64 + w] = a;
    }
    __syncthreads();
    if (tid < 64)
        q_s[tid] = qp[tid] + qp[64 + tid] + qp[128 + tid] + qp[192 + tid]
                   + __ldg(&bqkv[0]);
    __syncthreads();
    if (tid < 32) {
        float m = fmaxf(q_s[tid], q_s[tid + 32]);
        #pragma unroll
        for (int o = 16; o > 0; o >>= 1)
            m = fmaxf(m, __shfl_xor_sync(0xffffffffu, m, o));
        if (tid == 0) red[0] = m;
    }
    __syncthreads();
    if (tid < 64) q_s[tid] = __expf(q_s[tid] - red[0]);
    __syncthreads();
    if (tid < 32) {
        float s = q_s[tid] + q_s[tid + 32];
        #pragma unroll
        for (int o = 16; o > 0; o >>= 1) s += __shfl_xor_sync(0xffffffffu, s, o);
        if (tid == 0) red[1] = 1.0f / s;
    }
    __syncthreads();
    if (tid < 64) s_s[tid] = q_s[tid] * red[1];
    __syncthreads();

    {   // xs[c] = sum_w (Xh+Xl)[c,w] s[w]   (c = tid; rotated j: conflict-free)
        const __half2* XH2 = (const __half2*)(smc + OFF_XH);
        const __half2* XL2 = (const __half2*)(smc + OFF_SCR);
        float a = 0.f;
        #pragma unroll 8
        for (int j = 0; j < 32; j++) {
            int jj = (j + tid) & 31;
            float2 hf = __half22float2(XH2[tid * 36 + jj]);
            float2 lf = __half22float2(XL2[tid * 36 + jj]);
            a = fmaf(hf.x + lf.x, s_s[2 * jj], a);
            a = fmaf(hf.y + lf.y, s_s[2 * jj + 1], a);
        }
        xs_s[tid] = a;
    }

    // cv[c] = Wk[c,:].xs + bk[c]  (Xl region now dead -> reuse as Wks)
    float acc_cv = __ldg(&bqkv[1 + tid]);
    const float4* W4full = (const float4*)Wqkv;
    for (int ec = 0; ec < 8; ec++) {
        __syncthreads();
        #pragma unroll
        for (int i = 0; i < 8; i++) {
            int idx = tid + i * 256;
            int r = idx >> 3, q = idx & 7;
            float4 v = __ldg(&W4full[(size_t)(1 + r) * 64 + ec * 8 + q]);
            *(float4*)&Wks[r * 36 + q * 4] = v;
        }
        __syncthreads();
        #pragma unroll 8
        for (int e = 0; e < 32; e++) {
            int er = (e + tid) & 31;
            acc_cv = fmaf(Wks[tid * 36 + er], xs_s[ec * 32 + er], acc_cv);
        }
    }
    cv_s[tid] = acc_cv;
    __syncthreads();            // Wks reads done before A-chunk overwrite

    float acc[2][8][4];
    #pragma unroll
    for (int i = 0; i < 2; i++)
        #pragma unroll
        for (int j = 0; j < 8; j++)
            #pragma unroll
            for (int k = 0; k < 4; k++) acc[i][j][k] = 0.f;

    // ================= GEMM1: V = Wv . X =================
    gemm_main((const float4*)(Wqkv + (size_t)257 * 256), smc, smb, acc, tid);

    __syncthreads();            // B reads done before overwriting Xh with G
    {   // epi1: g = relu(v+bv)*cv -> Xh (fp16 hi)
        const int rb = wid * 32 + (lane >> 2);
        const int cb = 2 * (lane & 3);
        #pragma unroll
        for (int mf = 0; mf < 2; mf++)
            #pragma unroll
            for (int hf = 0; hf < 2; hf++) {
                int r = rb + 16 * mf + 8 * hf;
                float bv = __ldg(&bqkv[257 + r]);
                float cv = cv_s[r];
                #pragma unroll
                for (int nf = 0; nf < 8; nf++) {
                    float g0 = fmaxf(acc[mf][nf][2 * hf + 0] + bv, 0.f) * cv;
                    float g1 = fmaxf(acc[mf][nf][2 * hf + 1] + bv, 0.f) * cv;
                    uint32_t off = ((uint32_t)r * 72 + 8 * nf + cb) * 2;
                    *(uint32_t*)(smc + OFF_XH + off) = pack2h(g0, g1);
                }
            }
    }

    #pragma unroll
    for (int i = 0; i < 2; i++)
        #pragma unroll
        for (int j = 0; j < 8; j++)
            #pragma unroll
            for (int k = 0; k < 4; k++) acc[i][j][k] = 0.f;

    // ================= GEMM2: OUT = Wout . G =================
    gemm_main((const float4*)Wout, smc, smb, acc, tid);

    {   // epi2: + bout -> global out
        float* ob = out + (size_t)b * 1048576 + (size_t)h * 64;
        const int rb = wid * 32 + (lane >> 2);
        const int cb = 2 * (lane & 3);
        #pragma unroll
        for (int mf = 0; mf < 2; mf++)
            #pragma unroll
            for (int hf = 0; hf < 2; hf++) {
                int r = rb + 16 * mf + 8 * hf;
                float bo = __ldg(&bout[r]);
                #pragma unroll
                for (int nf = 0; nf < 8; nf++) {
                    float2 v;
                    v.x = acc[mf][nf][2 * hf + 0] + bo;
                    v.y = acc[mf][nf][2 * hf + 1] + bo;
                    *(float2*)(ob + (size_t)r * 4096 + 8 * nf + cb) = v;
                }
            }
    }
}

// ============================================================================
extern "C" void kernel_launch(void* const* d_in, const int* in_sizes, int n_in,
                              void* d_out, int out_size)
{
    const float* x    = (const float*)d_in[0];
    const float* Wqkv = (const float*)d_in[1];
    const float* bqkv = (const float*)d_in[2];
    const float* Wout = (const float*)d_in[3];
    const float* bout = (const float*)d_in[4];
    float* out = (float*)d_out;

    cudaFuncSetAttribute(sepattn_tc,
                         cudaFuncAttributeMaxDynamicSharedMemorySize, SMEM_BYTES);
    sepattn_tc<<<2048, 256, SMEM_BYTES>>>(x, Wqkv, bqkv, Wout, bout, out);
}

// round 10
// speedup vs baseline: 3.9533x; 1.6450x over previous
#include <cuda_runtime.h>
#include <cuda_fp16.h>
#include <cstdint>

// ============================================================================
// SeparableAttention — fused mma.sync fp16 kernel, round 10.
//   - W pre-split (prep kernel) into per-fragment fp16 hi/lo uint4s laid out
//     exactly as mma.m16n8k16 A-fragments -> A loads are single LDG.128,
//     no smem staging, no barriers in the k-loop.
//   - B (Xh fp16 tile) resident in smem, read via ldmatrix.trans.
//   - 2-term split: (Wh + Wl) . Xh   (numerics identical to round 9).
// ============================================================================

#define OFF_XH   0                         // Xh fp16 [256][72] = 36864 B
#define OFF_SCR  36864                     // Xl fp16 tile / Wks fp32 alias
#define OFF_TAIL 73728
#define SMEM_BYTES (OFF_TAIL + 8192)       // 81920 B -> 2 CTAs/SM

// W fragments: [gemm][half][ks][mtile][lane], mtile = 16-row M tile (16 of them)
__device__ uint4 sc_WF[2][2][16][16][32];  // 512 KB total
#define HOFF (16 * 16 * 32)                // half-to-half uint4 offset

// ---------------------------- helpers ---------------------------------------
__device__ __forceinline__ uint32_t smem_u32(const void* p) {
    uint32_t a;
    asm("{ .reg .u64 t; cvta.to.shared.u64 t, %1; cvt.u32.u64 %0, t; }"
        : "=r"(a) : "l"(p));
    return a;
}
__device__ __forceinline__ uint32_t pack2h(float a, float b) {
    __half2 t = __floats2half2_rn(a, b);
    return *reinterpret_cast<uint32_t*>(&t);
}
__device__ __forceinline__ float h_hi(float v) {
    return __half2float(__float2half_rn(v));
}

#define LDM4T(r0, r1, r2, r3, a) \
    asm volatile("ldmatrix.sync.aligned.m8n8.x4.trans.shared.b16 {%0,%1,%2,%3}, [%4];" \
        : "=r"(r0), "=r"(r1), "=r"(r2), "=r"(r3) : "r"(a))
#define MMA4(d, a, b) \
    asm volatile("mma.sync.aligned.m16n8k16.row.col.f32.f16.f16.f32 " \
        "{%0,%1,%2,%3}, {%4,%5,%6,%7}, {%8,%9}, {%0,%1,%2,%3};" \
        : "+f"((d)[0]), "+f"((d)[1]), "+f"((d)[2]), "+f"((d)[3]) \
        : "r"((a).x), "r"((a).y), "r"((a).z), "r"((a).w), \
          "r"((b)[0]), "r"((b)[1]))

// ============================================================================
// prep: build per-fragment fp16 hi/lo W tables.
// Fragment map (mma.m16n8k16, A row-major): lane l -> g=l>>2, t=l&3;
//   a0=(g, 2t),(g,2t+1)  a1=(g+8, 2t),(g+8,2t+1)
//   a2=(g, 2t+8),(g,2t+9)  a3=(g+8, 2t+8),(g+8,2t+9)
// ============================================================================
__global__ void prep_kernel(const float* __restrict__ Wqkv,
                            const float* __restrict__ Wout)
{
    int idx = blockIdx.x * 256 + threadIdx.x;   // 16384 threads
    int lane  = idx & 31;
    int mtile = (idx >> 5) & 15;
    int ks    = (idx >> 9) & 15;
    int gemm  = idx >> 13;
    const float* W = gemm ? Wout : (Wqkv + (size_t)257 * 256);

    int g = lane >> 2, t = lane & 3;
    int r0 = mtile * 16 + g, r1 = r0 + 8;
    int c0 = ks * 16 + 2 * t, c2 = c0 + 8;

    float w00 = W[r0 * 256 + c0], w01 = W[r0 * 256 + c0 + 1];
    float w10 = W[r1 * 256 + c0], w11 = W[r1 * 256 + c0 + 1];
    float w02 = W[r0 * 256 + c2], w03 = W[r0 * 256 + c2 + 1];
    float w12 = W[r1 * 256 + c2], w13 = W[r1 * 256 + c2 + 1];

    float h00 = h_hi(w00), h01 = h_hi(w01), h10 = h_hi(w10), h11 = h_hi(w11);
    float h02 = h_hi(w02), h03 = h_hi(w03), h12 = h_hi(w12), h13 = h_hi(w13);

    uint4 hi, lo;
    hi.x = pack2h(h00, h01); hi.y = pack2h(h10, h11);
    hi.z = pack2h(h02, h03); hi.w = pack2h(h12, h13);
    lo.x = pack2h(w00 - h00, w01 - h01); lo.y = pack2h(w10 - h10, w11 - h11);
    lo.z = pack2h(w02 - h02, w03 - h03); lo.w = pack2h(w12 - h12, w13 - h13);

    sc_WF[gemm][0][ks][mtile][lane] = hi;
    sc_WF[gemm][1][ks][mtile][lane] = lo;
}

// ============================================================================
// One 256x64x256 GEMM: A fragments via LDG.128 (double-buffered in regs),
// B = Xh smem tile via ldmatrix.trans. NO barriers inside.
// ============================================================================
__device__ __forceinline__ void gemm_main(const uint4* __restrict__ WF,
                                          uint32_t smb,
                                          float acc[2][8][4], int tid)
{
    const int lane = tid & 31, wid = tid >> 5;
    const int lrow = (lane & 7) + ((lane >> 3) & 1) * 8;
    const int lcol = (lane >> 4) * 8;

    uint4 bh[2][2], bl[2][2];
    #pragma unroll
    for (int mf = 0; mf < 2; mf++) {
        int off = (wid * 2 + mf) * 32 + lane;
        bh[0][mf] = __ldg(WF + off);
        bl[0][mf] = __ldg(WF + HOFF + off);
    }

    #pragma unroll
    for (int ks = 0; ks < 16; ks++) {
        const int p = ks & 1;
        if (ks < 15) {
            #pragma unroll
            for (int mf = 0; mf < 2; mf++) {
                int off = ((ks + 1) * 16 + wid * 2 + mf) * 32 + lane;
                bh[1 - p][mf] = __ldg(WF + off);
                bl[1 - p][mf] = __ldg(WF + HOFF + off);
            }
        }
        uint32_t Bh[8][2];
        const int k0 = ks * 16;
        #pragma unroll
        for (int nn = 0; nn < 4; nn++) {
            uint32_t boff = (uint32_t)(k0 + lrow) * 144 + (nn * 16 + lcol) * 2;
            uint32_t t0, t1, t2, t3;
            LDM4T(t0, t1, t2, t3, smb + OFF_XH + boff);
            Bh[2 * nn][0] = t0;     Bh[2 * nn][1] = t1;
            Bh[2 * nn + 1][0] = t2; Bh[2 * nn + 1][1] = t3;
        }
        #pragma unroll
        for (int mf = 0; mf < 2; mf++)
            #pragma unroll
            for (int nf = 0; nf < 8; nf++) {
                MMA4(acc[mf][nf], bh[p][mf], Bh[nf]);
                MMA4(acc[mf][nf], bl[p][mf], Bh[nf]);
            }
    }
}

// ============================================================================
__global__ __launch_bounds__(256, 2)
void sepattn_tc(const float* __restrict__ x,
                const float* __restrict__ Wqkv,
                const float* __restrict__ bqkv,
                const float* __restrict__ bout,
                float* __restrict__ out)
{
    extern __shared__ char smc[];
    float* tail = (float*)(smc + OFF_TAIL);
    float* cv_s = tail;                        // 256
    float* q_s  = tail + 256;                  // 64
    float* s_s  = tail + 320;                  // 64
    float* xs_s = tail + 384;                  // 256
    float* Wq_s = tail + 640;                  // 256
    float* qp   = tail + 896;                  // 256
    float* red  = tail + 1152;                 // 8
    float* Wks  = (float*)(smc + OFF_SCR);     // phase-1b alias over Xl
    const uint32_t smb = smem_u32(smc);

    const int tid = threadIdx.x;
    const int lane = tid & 31, wid = tid >> 5;
    const int b = blockIdx.x >> 6;
    const int h = blockIdx.x & 63;

    // -------- phase 0: load X tile, split Xh (fp16) + Xl (fp16) -------------
    const float2* x2 = (const float2*)(x + (size_t)b * 256 * 4096);
    #pragma unroll
    for (int k = 0; k < 32; k++) {
        int idx = tid + k * 256;
        int w2 = idx & 31, c = idx >> 5;
        float2 v = __ldg(&x2[c * 2048 + h * 32 + w2]);
        float h0 = h_hi(v.x), h1 = h_hi(v.y);
        uint32_t off = ((uint32_t)c * 72 + 2 * w2) * 2;
        *(uint32_t*)(smc + OFF_XH + off) = pack2h(h0, h1);
        *(uint32_t*)(smc + OFF_SCR + off) = pack2h(v.x - h0, v.y - h1);
    }
    if (tid < 64) {
        float4 v = __ldg(&((const float4*)Wqkv)[tid]);
        *(float4*)&Wq_s[4 * tid] = v;
    }
    __syncthreads();

    // -------- phase 1: q (256 thr), softmax, xs, cv -------------------------
    {
        int w = tid & 63, part = tid >> 6;
        const __half* XH = (const __half*)(smc + OFF_XH);
        const __half* XL = (const __half*)(smc + OFF_SCR);
        float a = 0.f;
        #pragma unroll 8
        for (int c = part * 64; c < part * 64 + 64; c++)
            a = fmaf(Wq_s[c],
                     __half2float(XH[c * 72 + w]) + __half2float(XL[c * 72 + w]),
                     a);
        qp[part * 64 + w] = a;
    }
    __syncthreads();
    if (tid < 64)
        q_s[tid] = qp[tid] + qp[64 + tid] + qp[128 + tid] + qp[192 + tid]
                   + __ldg(&bqkv[0]);
    __syncthreads();
    if (tid < 32) {
        float m = fmaxf(q_s[tid], q_s[tid + 32]);
        #pragma unroll
        for (int o = 16; o > 0; o >>= 1)
            m = fmaxf(m, __shfl_xor_sync(0xffffffffu, m, o));
        if (tid == 0) red[0] = m;
    }
    __syncthreads();
    if (tid < 64) q_s[tid] = __expf(q_s[tid] - red[0]);
    __syncthreads();
    if (tid < 32) {
        float s = q_s[tid] + q_s[tid + 32];
        #pragma unroll
        for (int o = 16; o > 0; o >>= 1) s += __shfl_xor_sync(0xffffffffu, s, o);
        if (tid == 0) red[1] = 1.0f / s;
    }
    __syncthreads();
    if (tid < 64) s_s[tid] = q_s[tid] * red[1];
    __syncthreads();

    {   // xs[c] = sum_w (Xh+Xl)[c,w] s[w]
        const __half2* XH2 = (const __half2*)(smc + OFF_XH);
        const __half2* XL2 = (const __half2*)(smc + OFF_SCR);
        float a = 0.f;
        #pragma unroll 8
        for (int j = 0; j < 32; j++) {
            int jj = (j + tid) & 31;
            float2 hf = __half22float2(XH2[tid * 36 + jj]);
            float2 lf = __half22float2(XL2[tid * 36 + jj]);
            a = fmaf(hf.x + lf.x, s_s[2 * jj], a);
            a = fmaf(hf.y + lf.y, s_s[2 * jj + 1], a);
        }
        xs_s[tid] = a;
    }

    // cv[c] = Wk[c,:].xs + bk[c]  (Xl dead -> Wks scratch)
    float acc_cv = __ldg(&bqkv[1 + tid]);
    const float4* W4full = (const float4*)Wqkv;
    for (int ec = 0; ec < 8; ec++) {
        __syncthreads();
        #pragma unroll
        for (int i = 0; i < 8; i++) {
            int idx = tid + i * 256;
            int r = idx >> 3, q = idx & 7;
            float4 v = __ldg(&W4full[(size_t)(1 + r) * 64 + ec * 8 + q]);
            *(float4*)&Wks[r * 36 + q * 4] = v;
        }
        __syncthreads();
        #pragma unroll 8
        for (int e = 0; e < 32; e++) {
            int er = (e + tid) & 31;
            acc_cv = fmaf(Wks[tid * 36 + er], xs_s[ec * 32 + er], acc_cv);
        }
    }
    cv_s[tid] = acc_cv;
    // cv_s visibility for epi1 is covered by the post-GEMM1 __syncthreads.

    float acc[2][8][4];
    #pragma unroll
    for (int i = 0; i < 2; i++)
        #pragma unroll
        for (int j = 0; j < 8; j++)
            #pragma unroll
            for (int k = 0; k < 4; k++) acc[i][j][k] = 0.f;

    // ================= GEMM1: V = Wv . X =================
    gemm_main(&sc_WF[0][0][0][0][0], smb, acc, tid);

    __syncthreads();            // all B reads done before overwriting Xh
    {   // epi1: g = relu(v+bv)*cv -> Xh
        const int rb = wid * 32 + (lane >> 2);
        const int cb = 2 * (lane & 3);
        #pragma unroll
        for (int mf = 0; mf < 2; mf++)
            #pragma unroll
            for (int hf = 0; hf < 2; hf++) {
                int r = rb + 16 * mf + 8 * hf;
                float bv = __ldg(&bqkv[257 + r]);
                float cv = cv_s[r];
                #pragma unroll
                for (int nf = 0; nf < 8; nf++) {
                    float g0 = fmaxf(acc[mf][nf][2 * hf + 0] + bv, 0.f) * cv;
                    float g1 = fmaxf(acc[mf][nf][2 * hf + 1] + bv, 0.f) * cv;
                    uint32_t off = ((uint32_t)r * 72 + 8 * nf + cb) * 2;
                    *(uint32_t*)(smc + OFF_XH + off) = pack2h(g0, g1);
                }
            }
    }
    __syncthreads();            // G tile visible to all warps

    #pragma unroll
    for (int i = 0; i < 2; i++)
        #pragma unroll
        for (int j = 0; j < 8; j++)
            #pragma unroll
            for (int k = 0; k < 4; k++) acc[i][j][k] = 0.f;

    // ================= GEMM2: OUT = Wout . G =================
    gemm_main(&sc_WF[1][0][0][0][0], smb, acc, tid);

    {   // epi2: + bout -> global out
        float* ob = out + (size_t)b * 1048576 + (size_t)h * 64;
        const int rb = wid * 32 + (lane >> 2);
        const int cb = 2 * (lane & 3);
        #pragma unroll
        for (int mf = 0; mf < 2; mf++)
            #pragma unroll
            for (int hf = 0; hf < 2; hf++) {
                int r = rb + 16 * mf + 8 * hf;
                float bo = __ldg(&bout[r]);
                #pragma unroll
                for (int nf = 0; nf < 8; nf++) {
                    float2 v;
                    v.x = acc[mf][nf][2 * hf + 0] + bo;
                    v.y = acc[mf][nf][2 * hf + 1] + bo;
                    *(float2*)(ob + (size_t)r * 4096 + 8 * nf + cb) = v;
                }
            }
    }
}

// ============================================================================
extern "C" void kernel_launch(void* const* d_in, const int* in_sizes, int n_in,
                              void* d_out, int out_size)
{
    const float* x    = (const float*)d_in[0];
    const float* Wqkv = (const float*)d_in[1];
    const float* bqkv = (const float*)d_in[2];
    const float* Wout = (const float*)d_in[3];
    const float* bout = (const float*)d_in[4];
    float* out = (float*)d_out;

    cudaFuncSetAttribute(sepattn_tc,
                         cudaFuncAttributeMaxDynamicSharedMemorySize, SMEM_BYTES);
    prep_kernel<<<64, 256>>>(Wqkv, Wout);
    sepattn_tc<<<2048, 256, SMEM_BYTES>>>(x, Wqkv, bqkv, bout, out);
}